// round 14
// baseline (speedup 1.0000x reference)
#include <cuda_runtime.h>

// Problem constants
constexpr int Bb  = 4;
constexpr int Hh  = 12;
constexpr int Ss  = 1024;
constexpr int Dd  = 768;
constexpr int HDd = 64;

// Scratch (allocation-free: __device__ globals)
__device__ float g_q[(size_t)Bb * Hh * Ss * HDd];     // [B,H,S,HD], pre-scaled by 1/8
__device__ float g_k[(size_t)Bb * Hh * Ss * HDd];     // [B,H,S,HD]
__device__ float g_v[(size_t)Bb * Hh * Ss * HDd];     // [B,H,S,HD]
__device__ float g_attn[(size_t)Bb * Ss * Dd];        // [B,S,D]

// ---------------------------------------------------------------------------
// 128x128x8 double-buffered SGEMM core: C = A[M,K] @ W[N,K]^T
// 256 threads, 8x8 per-thread microtile, warp layout 4x2, lane layout 4x8.
// ---------------------------------------------------------------------------
struct __align__(16) SmemGemm {
    float As[2][8][132];
    float Bs[2][8][132];
};

__device__ __forceinline__ void mm_step(const float (&As)[8][132],
                                        const float (&Bs)[8][132],
                                        int tr, int tc, float (&acc)[8][8])
{
    #pragma unroll
    for (int k = 0; k < 8; k++) {
        const float4 a0 = *(const float4*)&As[k][tr];
        const float4 a1 = *(const float4*)&As[k][tr + 4];
        const float4 b0 = *(const float4*)&Bs[k][tc];
        const float4 b1 = *(const float4*)&Bs[k][tc + 4];
        const float av[8] = {a0.x, a0.y, a0.z, a0.w, a1.x, a1.y, a1.z, a1.w};
        const float bv[8] = {b0.x, b0.y, b0.z, b0.w, b1.x, b1.y, b1.z, b1.w};
        #pragma unroll
        for (int i = 0; i < 8; i++)
            #pragma unroll
            for (int j = 0; j < 8; j++)
                acc[i][j] += av[i] * bv[j];
    }
}

__device__ __forceinline__ void gemm_core(SmemGemm& sm,
                                          const float* __restrict__ A,
                                          const float* __restrict__ W,
                                          int bm, int bn, int tr, int tc,
                                          float (&acc)[8][8])
{
    const int tid = threadIdx.x;
    const int lr  = tid >> 1;          // 0..127: tile row loaded by this thread
    const int lk  = (tid & 1) << 2;    // 0 or 4: k-segment

    const float* Ap = A + (size_t)(bm + lr) * Dd + lk;
    const float* Wp = W + (size_t)(bn + lr) * Dd + lk;

    #pragma unroll
    for (int i = 0; i < 8; i++)
        #pragma unroll
        for (int j = 0; j < 8; j++)
            acc[i][j] = 0.0f;

    // tile 0 -> buffer 0
    float4 pa = *(const float4*)Ap;
    float4 pb = *(const float4*)Wp;
    sm.As[0][lk + 0][lr] = pa.x; sm.As[0][lk + 1][lr] = pa.y;
    sm.As[0][lk + 2][lr] = pa.z; sm.As[0][lk + 3][lr] = pa.w;
    sm.Bs[0][lk + 0][lr] = pb.x; sm.Bs[0][lk + 1][lr] = pb.y;
    sm.Bs[0][lk + 2][lr] = pb.z; sm.Bs[0][lk + 3][lr] = pb.w;
    __syncthreads();

    constexpr int NT = Dd / 8;   // 96 k-tiles
    #pragma unroll 1
    for (int t = 0; t < NT - 1; t++) {
        const int koff = (t + 1) * 8;
        pa = *(const float4*)(Ap + koff);      // prefetch next tile (gmem)
        pb = *(const float4*)(Wp + koff);

        mm_step(sm.As[t & 1], sm.Bs[t & 1], tr, tc, acc);

        const int nb = (t + 1) & 1;
        sm.As[nb][lk + 0][lr] = pa.x; sm.As[nb][lk + 1][lr] = pa.y;
        sm.As[nb][lk + 2][lr] = pa.z; sm.As[nb][lk + 3][lr] = pa.w;
        sm.Bs[nb][lk + 0][lr] = pb.x; sm.Bs[nb][lk + 1][lr] = pb.y;
        sm.Bs[nb][lk + 2][lr] = pb.z; sm.Bs[nb][lk + 3][lr] = pb.w;
        __syncthreads();
    }
    mm_step(sm.As[(NT - 1) & 1], sm.Bs[(NT - 1) & 1], tr, tc, acc);
}

// ---------------------------------------------------------------------------
// Fused QKV projection: blockIdx.z selects {Q,K,V}; writes [B,H,S,HD] layout.
// Q is pre-scaled by HD^-0.5 = 0.125 (applies to bias too, matching reference).
// ---------------------------------------------------------------------------
__global__ __launch_bounds__(256, 2)
void qkv_kernel(const float* __restrict__ X,
                const float* __restrict__ Wq, const float* __restrict__ bq,
                const float* __restrict__ Wk, const float* __restrict__ bk,
                const float* __restrict__ Wv, const float* __restrict__ bv)
{
    __shared__ SmemGemm sm;

    const float* W;
    const float* bias;
    float* out;
    float scale;
    if (blockIdx.z == 0)      { W = Wq; bias = bq; out = g_q; scale = 0.125f; }
    else if (blockIdx.z == 1) { W = Wk; bias = bk; out = g_k; scale = 1.0f; }
    else                      { W = Wv; bias = bv; out = g_v; scale = 1.0f; }

    const int bm   = blockIdx.y * 128;
    const int bn   = blockIdx.x * 128;
    const int tid  = threadIdx.x;
    const int warp = tid >> 5, lane = tid & 31;
    const int tr = (warp >> 1) * 32 + (lane >> 3) * 8;
    const int tc = (warp & 1) * 64 + (lane & 7) * 8;

    float acc[8][8];
    gemm_core(sm, X, W, bm, bn, tr, tc, acc);

    float bb[8];
    #pragma unroll
    for (int j = 0; j < 8; j++) bb[j] = bias[bn + tc + j];

    #pragma unroll
    for (int i = 0; i < 8; i++) {
        const int mrow = bm + tr + i;
        const int bidx = mrow >> 10;      // / 1024
        const int srow = mrow & 1023;
        #pragma unroll
        for (int half = 0; half < 2; half++) {
            const int n = bn + tc + half * 4;
            const int h = n >> 6;         // / 64 (8-wide group never crosses head)
            const int d = n & 63;
            float4 o;
            o.x = (acc[i][half * 4 + 0] + bb[half * 4 + 0]) * scale;
            o.y = (acc[i][half * 4 + 1] + bb[half * 4 + 1]) * scale;
            o.z = (acc[i][half * 4 + 2] + bb[half * 4 + 2]) * scale;
            o.w = (acc[i][half * 4 + 3] + bb[half * 4 + 3]) * scale;
            *(float4*)&out[(((size_t)bidx * Hh + h) * Ss + srow) * HDd + d] = o;
        }
    }
}

// ---------------------------------------------------------------------------
// Flash-attention: one block per (q-tile of 64 rows, b*h). Causal: only
// key tiles j <= t are visited; diagonal tile masked exactly (exp -> 0, which
// matches the reference's  score + (-3^39)  mask bit-for-bit in fp32).
// Q,K stored d-major in smem (float4 operand reads); P transposed into K's
// slot for an all-float4 P@V pass. Online softmax with shfl-xor reductions.
// ---------------------------------------------------------------------------
__global__ __launch_bounds__(128, 3)
void attn_kernel()
{
    __shared__ __align__(16) float Qt[64][64];   // Qt[d][r]
    __shared__ __align__(16) float KPt[64][64];  // Kt[d][c], then Pt[c][r]
    __shared__ __align__(16) float Vs[64][64];   // V[c][d]

    const int tid = threadIdx.x;
    const int qt  = (int)(gridDim.x - 1 - blockIdx.x);  // heavy tiles first
    const int bh  = blockIdx.y;

    const float* Qb = g_q + ((size_t)bh * Ss + (size_t)qt * 64) * HDd;
    const float* Kb = g_k + (size_t)bh * Ss * HDd;
    const float* Vb = g_v + (size_t)bh * Ss * HDd;

    // Load Q tile transposed: Qt[d][r]
    #pragma unroll
    for (int it = 0; it < 8; it++) {
        const int idx = tid + it * 128;
        const int r   = idx >> 4;
        const int d0  = (idx & 15) << 2;
        const float4 v = *(const float4*)(Qb + r * HDd + d0);
        Qt[d0 + 0][r] = v.x; Qt[d0 + 1][r] = v.y;
        Qt[d0 + 2][r] = v.z; Qt[d0 + 3][r] = v.w;
    }

    const int ty = tid >> 3;       // 0..15 -> 4 query rows
    const int tx = tid & 7;        // 0..7  -> 8 key cols / 8 HD cols
    const int r0 = ty << 2;
    const int c0 = tx << 3;

    float m[4], l[4], O[4][8];
    #pragma unroll
    for (int i = 0; i < 4; i++) {
        m[i] = -1e30f; l[i] = 0.0f;
        #pragma unroll
        for (int j = 0; j < 8; j++) O[i][j] = 0.0f;
    }

    for (int jt = 0; jt <= qt; jt++) {
        __syncthreads();   // previous iteration's readers of KPt/Vs are done
        const float* Kj = Kb + (size_t)jt * 64 * HDd;
        const float* Vj = Vb + (size_t)jt * 64 * HDd;
        #pragma unroll
        for (int it = 0; it < 8; it++) {
            const int idx = tid + it * 128;
            const int r   = idx >> 4;
            const int d0  = (idx & 15) << 2;
            const float4 kv = *(const float4*)(Kj + r * HDd + d0);
            KPt[d0 + 0][r] = kv.x; KPt[d0 + 1][r] = kv.y;
            KPt[d0 + 2][r] = kv.z; KPt[d0 + 3][r] = kv.w;
            *(float4*)&Vs[r][d0] = *(const float4*)(Vj + r * HDd + d0);
        }
        __syncthreads();

        // S = Q @ K^T  (Q already carries the 1/sqrt(HD) scale)
        float s[4][8];
        #pragma unroll
        for (int i = 0; i < 4; i++)
            #pragma unroll
            for (int j = 0; j < 8; j++) s[i][j] = 0.0f;

        #pragma unroll 16
        for (int d = 0; d < 64; d++) {
            const float4 qv = *(const float4*)&Qt[d][r0];
            const float4 k0 = *(const float4*)&KPt[d][c0];
            const float4 k1 = *(const float4*)&KPt[d][c0 + 4];
            const float av[4]  = {qv.x, qv.y, qv.z, qv.w};
            const float bv2[8] = {k0.x, k0.y, k0.z, k0.w, k1.x, k1.y, k1.z, k1.w};
            #pragma unroll
            for (int i = 0; i < 4; i++)
                #pragma unroll
                for (int j = 0; j < 8; j++)
                    s[i][j] += av[i] * bv2[j];
        }

        if (jt == qt) {   // diagonal tile: causal mask
            #pragma unroll
            for (int i = 0; i < 4; i++)
                #pragma unroll
                for (int j = 0; j < 8; j++)
                    if (c0 + j > r0 + i) s[i][j] = -1e30f;
        }

        // online softmax (row stats replicated across the 8 tx lanes)
        #pragma unroll
        for (int i = 0; i < 4; i++) {
            float mx = s[i][0];
            #pragma unroll
            for (int j = 1; j < 8; j++) mx = fmaxf(mx, s[i][j]);
            mx = fmaxf(mx, __shfl_xor_sync(0xffffffffu, mx, 1));
            mx = fmaxf(mx, __shfl_xor_sync(0xffffffffu, mx, 2));
            mx = fmaxf(mx, __shfl_xor_sync(0xffffffffu, mx, 4));
            const float mn = fmaxf(m[i], mx);
            float sum = 0.0f;
            #pragma unroll
            for (int j = 0; j < 8; j++) {
                const float p = __expf(s[i][j] - mn);
                s[i][j] = p;
                sum += p;
            }
            sum += __shfl_xor_sync(0xffffffffu, sum, 1);
            sum += __shfl_xor_sync(0xffffffffu, sum, 2);
            sum += __shfl_xor_sync(0xffffffffu, sum, 4);
            const float alpha = __expf(m[i] - mn);
            l[i] = l[i] * alpha + sum;
            m[i] = mn;
            #pragma unroll
            for (int j = 0; j < 8; j++) O[i][j] *= alpha;
        }

        __syncthreads();   // all S-compute reads of KPt done
        // write P transposed into KPt: Pt[c][r]
        #pragma unroll
        for (int j = 0; j < 8; j++)
            #pragma unroll
            for (int i = 0; i < 4; i++)
                KPt[c0 + j][r0 + i] = s[i][j];
        __syncthreads();

        // O += P @ V
        #pragma unroll 16
        for (int k = 0; k < 64; k++) {
            const float4 pv = *(const float4*)&KPt[k][r0];
            const float4 v0 = *(const float4*)&Vs[k][c0];
            const float4 v1 = *(const float4*)&Vs[k][c0 + 4];
            const float pa[4]  = {pv.x, pv.y, pv.z, pv.w};
            const float vb2[8] = {v0.x, v0.y, v0.z, v0.w, v1.x, v1.y, v1.z, v1.w};
            #pragma unroll
            for (int i = 0; i < 4; i++)
                #pragma unroll
                for (int j = 0; j < 8; j++)
                    O[i][j] += pa[i] * vb2[j];
        }
    }

    // epilogue: normalize and write [B,S,D] (D index = h*64 + hd)
    const int b = bh / Hh;
    const int h = bh % Hh;
    #pragma unroll
    for (int i = 0; i < 4; i++) {
        const float inv = 1.0f / l[i];
        const int row = qt * 64 + r0 + i;
        float* op = g_attn + ((size_t)(b * Ss + row)) * Dd + h * HDd + c0;
        float4 o0, o1;
        o0.x = O[i][0] * inv; o0.y = O[i][1] * inv;
        o0.z = O[i][2] * inv; o0.w = O[i][3] * inv;
        o1.x = O[i][4] * inv; o1.y = O[i][5] * inv;
        o1.z = O[i][6] * inv; o1.w = O[i][7] * inv;
        *(float4*)op = o0;
        *(float4*)(op + 4) = o1;
    }
}

// ---------------------------------------------------------------------------
// Output projection: d_out[B*S, D] = g_attn @ Wo^T + bo
// ---------------------------------------------------------------------------
__global__ __launch_bounds__(256, 2)
void oproj_kernel(const float* __restrict__ Wo, const float* __restrict__ bo,
                  float* __restrict__ out)
{
    __shared__ SmemGemm sm;

    const int bm   = blockIdx.y * 128;
    const int bn   = blockIdx.x * 128;
    const int tid  = threadIdx.x;
    const int warp = tid >> 5, lane = tid & 31;
    const int tr = (warp >> 1) * 32 + (lane >> 3) * 8;
    const int tc = (warp & 1) * 64 + (lane & 7) * 8;

    float acc[8][8];
    gemm_core(sm, g_attn, Wo, bm, bn, tr, tc, acc);

    float bb[8];
    #pragma unroll
    for (int j = 0; j < 8; j++) bb[j] = bo[bn + tc + j];

    #pragma unroll
    for (int i = 0; i < 8; i++) {
        const int mrow = bm + tr + i;
        float* op = out + (size_t)mrow * Dd + bn + tc;
        float4 o0, o1;
        o0.x = acc[i][0] + bb[0]; o0.y = acc[i][1] + bb[1];
        o0.z = acc[i][2] + bb[2]; o0.w = acc[i][3] + bb[3];
        o1.x = acc[i][4] + bb[4]; o1.y = acc[i][5] + bb[5];
        o1.z = acc[i][6] + bb[6]; o1.w = acc[i][7] + bb[7];
        *(float4*)op = o0;
        *(float4*)(op + 4) = o1;
    }
}

// ---------------------------------------------------------------------------
extern "C" void kernel_launch(void* const* d_in, const int* in_sizes, int n_in,
                              void* d_out, int out_size)
{
    (void)in_sizes; (void)n_in; (void)out_size;
    const float* hs = (const float*)d_in[0];
    const float* Wq = (const float*)d_in[1];
    const float* bq = (const float*)d_in[2];
    const float* Wk = (const float*)d_in[3];
    const float* bk = (const float*)d_in[4];
    const float* Wv = (const float*)d_in[5];
    const float* bv = (const float*)d_in[6];
    const float* Wo = (const float*)d_in[7];
    const float* bo = (const float*)d_in[8];

    dim3 qkvGrid(Dd / 128, (Bb * Ss) / 128, 3);   // (6, 32, 3)
    qkv_kernel<<<qkvGrid, 256>>>(hs, Wq, bq, Wk, bk, Wv, bv);

    attn_kernel<<<dim3(Ss / 64, Bb * Hh), 128>>>();  // (16, 48)

    dim3 oGrid(Dd / 128, (Bb * Ss) / 128);        // (6, 32)
    oproj_kernel<<<oGrid, 256>>>(Wo, bo, (float*)d_out);
}